// round 11
// baseline (speedup 1.0000x reference)
#include <cuda_runtime.h>

static constexpr int K = 32;
static constexpr int ROWS_PER_THREAD = 2;
static constexpr int THREADS = 256;

__global__ __launch_bounds__(THREADS)
void bignet_kernel(const float4* __restrict__ x4,
                   const float4* __restrict__ W4,   // [K] float4 (each row of W)
                   const float*  __restrict__ b,    // [K]
                   float* __restrict__ out,         // [K, N]
                   int N)
{
    __shared__ float4 sW[K];
    __shared__ float  sb[K];
    if (threadIdx.x < K) {
        sW[threadIdx.x] = W4[threadIdx.x];
        sb[threadIdx.x] = b[threadIdx.x];
    }
    __syncthreads();

    int t  = blockIdx.x * blockDim.x + threadIdx.x;
    int n0 = t * ROWS_PER_THREAD;
    if (n0 >= N) return;

    if (n0 + ROWS_PER_THREAD <= N) {
        // Fast path: 2 rows per thread -> one float2 store per plane.
        float4 r0 = x4[n0 + 0];
        float4 r1 = x4[n0 + 1];

        #pragma unroll
        for (int k = 0; k < K; k++) {
            float4 w  = sW[k];
            float  bb = sb[k];
            float2 o;
            o.x = fmaf(r0.x, w.x, fmaf(r0.y, w.y, fmaf(r0.z, w.z, fmaf(r0.w, w.w, bb))));
            o.y = fmaf(r1.x, w.x, fmaf(r1.y, w.y, fmaf(r1.z, w.z, fmaf(r1.w, w.w, bb))));
            *reinterpret_cast<float2*>(out + (size_t)k * N + n0) = o;
        }
    } else {
        // Tail path: per-row scalar stores.
        for (int r = 0; r < ROWS_PER_THREAD; r++) {
            int n = n0 + r;
            if (n >= N) break;
            float4 xr = x4[n];
            #pragma unroll
            for (int k = 0; k < K; k++) {
                float4 w  = sW[k];
                float  bb = sb[k];
                float  o  = fmaf(xr.x, w.x, fmaf(xr.y, w.y, fmaf(xr.z, w.z, fmaf(xr.w, w.w, bb))));
                out[(size_t)k * N + n] = o;
            }
        }
    }
}

extern "C" void kernel_launch(void* const* d_in, const int* in_sizes, int n_in,
                              void* d_out, int out_size)
{
    const float* x = (const float*)d_in[0];   // [N, 4]
    const float* W = (const float*)d_in[1];   // [K, 1, 4]
    const float* b = (const float*)d_in[2];   // [K, 1]
    float* out = (float*)d_out;               // [K, N, 1]

    int N = in_sizes[0] / 4;

    int threads_needed = (N + ROWS_PER_THREAD - 1) / ROWS_PER_THREAD;
    int blocks = (threads_needed + THREADS - 1) / THREADS;

    bignet_kernel<<<blocks, THREADS>>>(
        (const float4*)x, (const float4*)W, b, out, N);
}